// round 2
// baseline (speedup 1.0000x reference)
#include <cuda_runtime.h>
#include <cuda_bf16.h>
#include <cstdint>

#define N_NODES 50000
#define IN_FEAT 256
#define NHEAD   4
#define DH      64
#define NREL    6
#define NEDGE   300000
#define OUTF    256   // NHEAD*DH
#define NEG_SLOPE 0.2f

// ---------------- scratch (device globals; no runtime allocation) ----------
__device__ float    g_feat[(size_t)NREL * N_NODES * OUTF];   // 307 MB
__device__ float    g_agg [(size_t)NREL * N_NODES * OUTF];   // 307 MB
__device__ float    g_el  [(size_t)NREL * N_NODES * NHEAD];
__device__ float    g_er  [(size_t)NREL * N_NODES * NHEAD];
__device__ unsigned g_mkey[(size_t)NREL * N_NODES * NHEAD];
__device__ float    g_z   [(size_t)NREL * N_NODES * NHEAD];
__device__ float    g_e   [(size_t)NREL * NEDGE   * NHEAD];  // scores, then a

// monotone float<->uint encoding so atomicMax(uint) == float max
__device__ __forceinline__ unsigned enc_f(float f) {
    unsigned b = __float_as_uint(f);
    return (b & 0x80000000u) ? ~b : (b | 0x80000000u);
}
__device__ __forceinline__ float dec_f(unsigned k) {
    unsigned b = (k & 0x80000000u) ? (k ^ 0x80000000u) : ~k;
    return __uint_as_float(b);
}

// ---------------- 1. init --------------------------------------------------
__global__ void init_kernel() {
    size_t i      = (size_t)blockIdx.x * blockDim.x + threadIdx.x;
    size_t stride = (size_t)gridDim.x * blockDim.x;
    const size_t agg4 = (size_t)NREL * N_NODES * OUTF / 4;
    float4* a4 = reinterpret_cast<float4*>(g_agg);
    float4  zz = make_float4(0.f, 0.f, 0.f, 0.f);
    for (size_t j = i; j < agg4; j += stride) a4[j] = zz;
    const size_t nh = (size_t)NREL * N_NODES * NHEAD;
    for (size_t j = i; j < nh; j += stride) { g_z[j] = 0.f; g_mkey[j] = 0u; }
}

// ---------------- 2. batched GEMM  feat[r] = x @ W[r] ----------------------
#define BM 128
#define BN 64
#define BK 16
__global__ __launch_bounds__(256) void gemm_kernel(const float* __restrict__ x,
                                                   const float* __restrict__ W) {
    __shared__ float As[BK][BM];   // transposed x tile
    __shared__ float Bs[BK][BN];

    const int r    = blockIdx.z;
    const int col0 = blockIdx.y * BN;
    const int row0 = blockIdx.x * BM;
    const float* Wr = W + (size_t)r * IN_FEAT * OUTF;
    float* C = g_feat + (size_t)r * N_NODES * OUTF;

    const int tid = threadIdx.x;
    const int tx  = tid & 15;       // 0..15 -> col0 + tx*4
    const int ty  = tid >> 4;       // 0..15 -> row0 + ty*8

    float acc[8][4];
#pragma unroll
    for (int i = 0; i < 8; i++)
#pragma unroll
        for (int j = 0; j < 4; j++) acc[i][j] = 0.f;

    for (int kt = 0; kt < IN_FEAT; kt += BK) {
        // load As: 128 rows x 16 cols  (512 float4 slots, 2 per thread)
#pragma unroll
        for (int i = 0; i < 2; i++) {
            int slot = tid + i * 256;
            int rl   = slot >> 2;
            int c4   = slot & 3;
            int grow = row0 + rl;
            float4 v = make_float4(0.f, 0.f, 0.f, 0.f);
            if (grow < N_NODES)
                v = *reinterpret_cast<const float4*>(&x[(size_t)grow * IN_FEAT + kt + c4 * 4]);
            As[c4 * 4 + 0][rl] = v.x;
            As[c4 * 4 + 1][rl] = v.y;
            As[c4 * 4 + 2][rl] = v.z;
            As[c4 * 4 + 3][rl] = v.w;
        }
        // load Bs: 16 rows x 64 cols (256 float4 slots, 1 per thread)
        {
            int rowk = tid >> 4;
            int c4b  = tid & 15;
            float4 w = *reinterpret_cast<const float4*>(
                &Wr[(size_t)(kt + rowk) * OUTF + col0 + c4b * 4]);
            *reinterpret_cast<float4*>(&Bs[rowk][c4b * 4]) = w;
        }
        __syncthreads();
#pragma unroll
        for (int k = 0; k < BK; k++) {
            float4 a0 = *reinterpret_cast<const float4*>(&As[k][ty * 8]);
            float4 a1 = *reinterpret_cast<const float4*>(&As[k][ty * 8 + 4]);
            float4 b0 = *reinterpret_cast<const float4*>(&Bs[k][tx * 4]);
            float av[8] = {a0.x, a0.y, a0.z, a0.w, a1.x, a1.y, a1.z, a1.w};
            float bv[4] = {b0.x, b0.y, b0.z, b0.w};
#pragma unroll
            for (int i = 0; i < 8; i++)
#pragma unroll
                for (int j = 0; j < 4; j++)
                    acc[i][j] = fmaf(av[i], bv[j], acc[i][j]);
        }
        __syncthreads();
    }
#pragma unroll
    for (int i = 0; i < 8; i++) {
        int grow = row0 + ty * 8 + i;
        if (grow < N_NODES) {
            float4 v = make_float4(acc[i][0], acc[i][1], acc[i][2], acc[i][3]);
            *reinterpret_cast<float4*>(&C[(size_t)grow * OUTF + col0 + tx * 4]) = v;
        }
    }
}

// ---------------- 3. attention dots el/er ----------------------------------
__global__ void attn_kernel(const float* __restrict__ attn_l,
                            const float* __restrict__ attn_r) {
    int gw   = (blockIdx.x * blockDim.x + threadIdx.x) >> 5;
    int lane = threadIdx.x & 31;
    const int total = NREL * N_NODES * NHEAD;
    if (gw >= total) return;
    int h = gw % NHEAD;
    int n = (gw / NHEAD) % N_NODES;
    int r = gw / (NHEAD * N_NODES);
    const float* f = g_feat + ((size_t)r * N_NODES + n) * OUTF + h * DH;
    const float* al = attn_l + (r * NHEAD + h) * DH;
    const float* ar = attn_r + (r * NHEAD + h) * DH;
    float v0 = f[lane], v1 = f[lane + 32];
    float sl = v0 * al[lane] + v1 * al[lane + 32];
    float sr = v0 * ar[lane] + v1 * ar[lane + 32];
#pragma unroll
    for (int o = 16; o > 0; o >>= 1) {
        sl += __shfl_xor_sync(0xffffffffu, sl, o);
        sr += __shfl_xor_sync(0xffffffffu, sr, o);
    }
    if (lane == 0) { g_el[gw] = sl; g_er[gw] = sr; }
}

// ---------------- 4. edge scores + segment max ------------------------------
__global__ void edge1_kernel(const int* __restrict__ src,
                             const int* __restrict__ dst) {
    int i = blockIdx.x * blockDim.x + threadIdx.x;
    if (i >= NREL * NEDGE) return;
    int r = i / NEDGE;
    int s = src[i];
    int d = dst[i];
    if ((unsigned)s >= N_NODES || (unsigned)d >= N_NODES) return; // defensive
    float4 l4 = *reinterpret_cast<const float4*>(&g_el[((size_t)r * N_NODES + s) * NHEAD]);
    float4 r4 = *reinterpret_cast<const float4*>(&g_er[((size_t)r * N_NODES + d) * NHEAD]);
    float ev[4] = {l4.x + r4.x, l4.y + r4.y, l4.z + r4.z, l4.w + r4.w};
#pragma unroll
    for (int h = 0; h < 4; h++) ev[h] = (ev[h] > 0.f) ? ev[h] : NEG_SLOPE * ev[h];
    *reinterpret_cast<float4*>(&g_e[(size_t)i * NHEAD]) =
        make_float4(ev[0], ev[1], ev[2], ev[3]);
    unsigned* mk = &g_mkey[((size_t)r * N_NODES + d) * NHEAD];
#pragma unroll
    for (int h = 0; h < 4; h++) atomicMax(&mk[h], enc_f(ev[h]));
}

// ---------------- 5. exp + segment sum --------------------------------------
__global__ void edge2_kernel(const int* __restrict__ dst) {
    int i = blockIdx.x * blockDim.x + threadIdx.x;
    if (i >= NREL * NEDGE) return;
    int r = i / NEDGE;
    int d = dst[i];
    if ((unsigned)d >= N_NODES) return; // defensive
    size_t nb = ((size_t)r * N_NODES + d) * NHEAD;
    float4 ev = *reinterpret_cast<const float4*>(&g_e[(size_t)i * NHEAD]);
    uint4  mk = *reinterpret_cast<const uint4*>(&g_mkey[nb]);
    float a0 = __expf(ev.x - dec_f(mk.x));
    float a1 = __expf(ev.y - dec_f(mk.y));
    float a2 = __expf(ev.z - dec_f(mk.z));
    float a3 = __expf(ev.w - dec_f(mk.w));
    *reinterpret_cast<float4*>(&g_e[(size_t)i * NHEAD]) = make_float4(a0, a1, a2, a3);
    atomicAdd(&g_z[nb + 0], a0);
    atomicAdd(&g_z[nb + 1], a1);
    atomicAdd(&g_z[nb + 2], a2);
    atomicAdd(&g_z[nb + 3], a3);
}

// ---------------- 6. weighted scatter (warp per edge) -----------------------
__global__ void edge3_kernel(const int* __restrict__ src,
                             const int* __restrict__ dst) {
    int gw   = (blockIdx.x * blockDim.x + threadIdx.x) >> 5;
    int lane = threadIdx.x & 31;
    if (gw >= NREL * NEDGE) return;
    int r = gw / NEDGE;
    int s = src[gw];
    int d = dst[gw];
    if ((unsigned)s >= N_NODES || (unsigned)d >= N_NODES) return; // defensive
    float4 a4 = *reinterpret_cast<const float4*>(&g_e[(size_t)gw * NHEAD]);
    float4 z4 = *reinterpret_cast<const float4*>(&g_z[((size_t)r * N_NODES + d) * NHEAD]);
    float alpha[4] = {a4.x / fmaxf(z4.x, 1e-9f), a4.y / fmaxf(z4.y, 1e-9f),
                      a4.z / fmaxf(z4.z, 1e-9f), a4.w / fmaxf(z4.w, 1e-9f)};
    const float4* fs = reinterpret_cast<const float4*>(
        &g_feat[((size_t)r * N_NODES + s) * OUTF]);
    float* ad = &g_agg[((size_t)r * N_NODES + d) * OUTF];
#pragma unroll
    for (int it = 0; it < 2; it++) {
        int c4 = lane + 32 * it;          // 0..63
        float4 f = fs[c4];
        float  al = alpha[c4 >> 4];
        int    c  = c4 * 4;
        atomicAdd(ad + c + 0, al * f.x);
        atomicAdd(ad + c + 1, al * f.y);
        atomicAdd(ad + c + 2, al * f.z);
        atomicAdd(ad + c + 3, al * f.w);
    }
}

// ---------------- 7. combine relations + final relu -------------------------
__global__ void final_kernel(const float* __restrict__ bias, float* __restrict__ out) {
    int i = blockIdx.x * blockDim.x + threadIdx.x;   // float4 index
    const int total4 = N_NODES * OUTF / 4;
    if (i >= total4) return;
    int c4 = i & 63;
    int n  = i >> 6;
    float4 acc = make_float4(0.f, 0.f, 0.f, 0.f);
#pragma unroll
    for (int r = 0; r < NREL; r++) {
        float4 g = *reinterpret_cast<const float4*>(
            &g_agg[((size_t)r * N_NODES + n) * OUTF + c4 * 4]);
        float4 b = *reinterpret_cast<const float4*>(&bias[r * OUTF + c4 * 4]);
        acc.x += fmaxf(g.x + b.x, 0.f);
        acc.y += fmaxf(g.y + b.y, 0.f);
        acc.z += fmaxf(g.z + b.z, 0.f);
        acc.w += fmaxf(g.w + b.w, 0.f);
    }
    acc.x = fmaxf(acc.x, 0.f);
    acc.y = fmaxf(acc.y, 0.f);
    acc.z = fmaxf(acc.z, 0.f);
    acc.w = fmaxf(acc.w, 0.f);
    reinterpret_cast<float4*>(out)[i] = acc;
}

// ---------------- launch -----------------------------------------------------
extern "C" void kernel_launch(void* const* d_in, const int* in_sizes, int n_in,
                              void* d_out, int out_size) {
    (void)in_sizes; (void)n_in; (void)out_size;
    const float* x      = (const float*)d_in[0];
    const float* W      = (const float*)d_in[1];
    const float* attn_l = (const float*)d_in[2];
    const float* attn_r = (const float*)d_in[3];
    const float* bias   = (const float*)d_in[4];
    const int*   src    = (const int*)d_in[5];
    const int*   dst    = (const int*)d_in[6];
    float*       out    = (float*)d_out;

    init_kernel<<<2048, 256>>>();

    dim3 gg((N_NODES + BM - 1) / BM, OUTF / BN, NREL);
    gemm_kernel<<<gg, 256>>>(x, W);

    {
        long long warps = (long long)NREL * N_NODES * NHEAD;
        int blocks = (int)((warps * 32 + 255) / 256);
        attn_kernel<<<blocks, 256>>>(attn_l, attn_r);
    }

    int ne = NREL * NEDGE;
    edge1_kernel<<<(ne + 255) / 256, 256>>>(src, dst);
    edge2_kernel<<<(ne + 255) / 256, 256>>>(dst);

    {
        long long thr = (long long)ne * 32;
        int blocks = (int)((thr + 255) / 256);
        edge3_kernel<<<blocks, 256>>>(src, dst);
    }

    final_kernel<<<(N_NODES * OUTF / 4 + 255) / 256, 256>>>(bias, out);
}